// round 14
// baseline (speedup 1.0000x reference)
#include <cuda_runtime.h>
#include <cstdint>

#define LNUM 24
#define BB 32
#define DD 1024
#define ED 2048
#define NN 16
#define RR 64
#define VV 50280
#define NBLK 148
#define NTHR 1024
#define NSB (NBLK*8)
#define SBSTRIDE 5760            // floats per subblock: xs(1152) + 2x wbuf(2304)
#define SMEM_BYTES (8 * SBSTRIDE * 4)
#define XZP_OFF (2*ED*BB)        // 131072 floats per in_proj partial
#define XP_OFF  (DD*BB)          // 32768 floats per out_proj partial

typedef unsigned long long ull;

// -------- persistent scratch (feature-major, batch-minor [feat][32]) --------
__device__ float g_x  [DD*BB];
__device__ float g_xzp[8  * XZP_OFF];   // in_proj split-K partials (4MB)
__device__ float g_xp [16 * XP_OFF];    // out_proj split-K partials (2MB)
__device__ float g_xc [ED*BB];
__device__ float g_dbc[(RR+2*NN)*BB];
__device__ float g_g  [ED*BB];
__device__ float g_sspart[32*BB];       // per-block sum-of-squares partials
__device__ float g_rms[BB];             // rsqrt(mean(x^2)+eps) per batch
__device__ float g_lp0[BB*VV];
__device__ float g_lp1[BB*VV];
__device__ int   g_flags[NBLK];
__device__ int   g_release;

// -------- f32x2 helpers --------
__device__ __forceinline__ ull dup2(float w) {
    ull r; asm("mov.b64 %0, {%1, %1};" : "=l"(r) : "f"(w)); return r;
}
__device__ __forceinline__ void fma2(ull &a, ull x, ull y) {
    asm("fma.rn.f32x2 %0, %1, %2, %0;" : "+l"(a) : "l"(x), "l"(y));
}
__device__ __forceinline__ float2 unpack2(ull v) {
    float lo, hi; asm("mov.b64 {%0, %1}, %2;" : "=f"(lo), "=f"(hi) : "l"(v));
    return make_float2(lo, hi);
}
__device__ __forceinline__ float sigf(float z) { return 1.f / (1.f + __expf(-z)); }

// -------- cp.async helpers --------
__device__ __forceinline__ void cpasync16(float* smem_dst, const float* gptr) {
    uint32_t a = (uint32_t)__cvta_generic_to_shared(smem_dst);
    asm volatile("cp.async.ca.shared.global [%0], [%1], 16;" :: "r"(a), "l"(gptr));
}
__device__ __forceinline__ void cpcommit() {
    asm volatile("cp.async.commit_group;");
}
template<int N>
__device__ __forceinline__ void cpwait() {
    asm volatile("cp.async.wait_group %0;" :: "n"(N));
}

__device__ __forceinline__ void barsub(int sbl) {
    asm volatile("bar.sync %0, %1;" :: "r"(sbl + 1), "r"(128) : "memory");
}

// -------- flag-based grid barrier (replay-safe via init-read) --------
__device__ __forceinline__ void gsync(int &gen) {
    __syncthreads();
    if (threadIdx.x == 0) {
        __threadfence();
        ((volatile int*)g_flags)[blockIdx.x] = gen + 1;
    }
    if (blockIdx.x == 0) {
        if (threadIdx.x < NBLK) {
            while (((volatile int*)g_flags)[threadIdx.x] - (gen + 1) < 0) { }
        }
        __syncthreads();
        if (threadIdx.x == 0) {
            __threadfence();
            *(volatile int*)&g_release = gen + 1;
        }
    } else {
        if (threadIdx.x == 0) {
            while (*(volatile int*)&g_release - (gen + 1) < 0) { }
            __threadfence();
        }
    }
    __syncthreads();
    gen = gen + 1;
}

// ---------------------------------------------------------------------------
// subblock GEMM: partial[ks][M][32] = W[M][k0:k0+klen] * X[k0:k0+klen][32]
// Tile = 64 rows x 32 b x klen; thread tile 2 rows x 8 b (8 f32x2 accs).
// W streamed GMEM->SMEM via coalesced cp.async, double-buffered.
// NO atomics: every (ks,row,b) written by exactly one thread.
// MODE 0: X = g_x * nw[k],  OUT = g_xzp + ks*XZP_OFF  (in_proj)
// MODE 1: X = g_g,          OUT = g_xp  + ks*XP_OFF   (out_proj)
// MODE 2: X = g_x * nw[k],  OUT = logits / g_lp0 / g_lp1 (K-split 3, strided)
// ---------------------------------------------------------------------------
template<int MODE>
__device__ void gemm_stage(const float* __restrict__ W, float* __restrict__ OUT,
                           const float* __restrict__ nw,
                           int M, int Kdim, int kslice, int ksplit, int ntiles,
                           float* __restrict__ sh) {
    int lt  = threadIdx.x & 127;
    int sbl = threadIdx.x >> 7;
    int sb  = sbl * NBLK + blockIdx.x;
    int bg  = lt & 3, rg = lt >> 2;       // rg 0..31 -> 2 rows each
    int b0  = bg * 8;
    int lb  = lt & 31, kq = lt >> 5;
    float* xs  = sh + sbl * SBSTRIDE;     // 32 x 36
    float* wb0 = xs + 1152;               // 64 x 36
    float* wb1 = wb0 + 2304;              // 64 x 36
    int r_a = lt >> 3, c_a = lt & 7;      // cp.async: 4 rows/thread, coalesced

    for (int t = sb; t < ntiles; t += NSB) {
        int mt, ks, k0, klen;
        if (MODE == 2) {
            mt = t / 3; ks = t - mt * 3;
            k0 = ks * 352; klen = (ks == 2) ? 320 : 352;
        } else {
            mt = t / ksplit; ks = t - mt * ksplit;
            k0 = ks * kslice; klen = kslice;
        }
        int rbase = mt * 64;

        const float* wg[4];
        float* wd[4];
        #pragma unroll
        for (int j = 0; j < 4; j++) {
            int ra = rbase + r_a + j * 16; if (ra > M - 1) ra = M - 1;
            wg[j] = W + (size_t)ra * Kdim + k0 + c_a * 4;
            wd[j] = wb0 + (r_a + j * 16) * 36 + c_a * 4;
        }
        int nchunks = klen >> 5;

        // prologue: chunk 0 -> buf0
        #pragma unroll
        for (int j = 0; j < 4; j++) cpasync16(wd[j], wg[j]);
        cpcommit();

        ull acc[8];
        #pragma unroll
        for (int j = 0; j < 8; j++) acc[j] = 0ULL;

        for (int c = 0; c < nchunks; c++) {
            int kc = c << 5;
            // stage x chunk (coalesced: lanes along b; nw warp-uniform)
            #pragma unroll
            for (int i = 0; i < 8; i++) {
                int kk = kq + 4*i;
                int kgl = k0 + kc + kk;
                float v;
                if (MODE == 1) v = g_g[kgl*32 + lb];
                else           v = g_x[kgl*32 + lb] * nw[kgl];
                xs[kk*36 + lb] = v;
            }
            if (c + 1 < nchunks) {
                int off = 2304 * ((c + 1) & 1);
                #pragma unroll
                for (int j = 0; j < 4; j++)
                    cpasync16(wd[j] + off, wg[j] + kc + 32);
                cpcommit();
                cpwait<1>();
            } else {
                cpwait<0>();
            }
            barsub(sbl);

            const float* wb = (c & 1) ? wb1 : wb0;
            const float* wrA = wb + (rg*2) * 36;
            const float* wrB = wrA + 36;
            #pragma unroll
            for (int q = 0; q < 8; q++) {
                float4 wa = *(const float4*)(wrA + q*4);
                float4 wv = *(const float4*)(wrB + q*4);
                #pragma unroll
                for (int tt = 0; tt < 4; tt++) {
                    int kk = q*4 + tt;
                    ulonglong2 q0 = *(const ulonglong2*)&xs[kk*36 + b0];
                    ulonglong2 q1 = *(const ulonglong2*)&xs[kk*36 + b0 + 4];
                    float fa = (tt==0)?wa.x:(tt==1)?wa.y:(tt==2)?wa.z:wa.w;
                    float fb = (tt==0)?wv.x:(tt==1)?wv.y:(tt==2)?wv.z:wv.w;
                    ull da = dup2(fa), db = dup2(fb);
                    fma2(acc[0], da, q0.x); fma2(acc[1], da, q0.y);
                    fma2(acc[2], da, q1.x); fma2(acc[3], da, q1.y);
                    fma2(acc[4], db, q0.x); fma2(acc[5], db, q0.y);
                    fma2(acc[6], db, q1.x); fma2(acc[7], db, q1.y);
                }
            }
            barsub(sbl);
        }

        int r0 = rbase + rg*2, r1 = r0 + 1;
        if (MODE == 2) {
            float* outp = (ks == 0) ? OUT : ((ks == 1) ? g_lp0 : g_lp1);
            #pragma unroll
            for (int rr = 0; rr < 2; rr++) {
                int r = (rr == 0) ? r0 : r1;
                if (r < M) {
                    float2 a0 = unpack2(acc[rr*4+0]), a1 = unpack2(acc[rr*4+1]);
                    float2 a2 = unpack2(acc[rr*4+2]), a3 = unpack2(acc[rr*4+3]);
                    outp[(size_t)(b0+0)*VV + r] = a0.x;
                    outp[(size_t)(b0+1)*VV + r] = a0.y;
                    outp[(size_t)(b0+2)*VV + r] = a1.x;
                    outp[(size_t)(b0+3)*VV + r] = a1.y;
                    outp[(size_t)(b0+4)*VV + r] = a2.x;
                    outp[(size_t)(b0+5)*VV + r] = a2.y;
                    outp[(size_t)(b0+6)*VV + r] = a3.x;
                    outp[(size_t)(b0+7)*VV + r] = a3.y;
                }
            }
        } else {
            float* outp = OUT + (size_t)ks * ((MODE == 0) ? XZP_OFF : XP_OFF);
            #pragma unroll
            for (int rr = 0; rr < 2; rr++) {
                int r = (rr == 0) ? r0 : r1;
                float2 a0 = unpack2(acc[rr*4+0]), a1 = unpack2(acc[rr*4+1]);
                float2 a2 = unpack2(acc[rr*4+2]), a3 = unpack2(acc[rr*4+3]);
                *(float4*)&outp[r*32 + b0]     = make_float4(a0.x, a0.y, a1.x, a1.y);
                *(float4*)&outp[r*32 + b0 + 4] = make_float4(a2.x, a2.y, a3.x, a3.y);
            }
        }
    }
}

// rms reduce: one warp folds 32 per-block partials into g_rms
__device__ __forceinline__ void rms_reduce() {
    if (blockIdx.x == 0 && threadIdx.x < 32) {
        float s = 0.f;
        #pragma unroll
        for (int j = 0; j < 32; j++) s += g_sspart[j*32 + threadIdx.x];
        g_rms[threadIdx.x] = rsqrtf(s * (1.f/(float)DD) + 1e-5f);
    }
}

// ---------------------------------------------------------------------------
__global__ __launch_bounds__(NTHR, 1)
void mega_kernel(const int* __restrict__ token, const float* __restrict__ hs,
                 const float* __restrict__ ci, const float* __restrict__ emb,
                 const float* __restrict__ norm_w, const float* __restrict__ ipw,
                 const float* __restrict__ cw, const float* __restrict__ cb,
                 const float* __restrict__ xpw, const float* __restrict__ dtw,
                 const float* __restrict__ dtb, const float* __restrict__ alog,
                 const float* __restrict__ Dp, const float* __restrict__ opw,
                 const float* __restrict__ nfw,
                 float* __restrict__ logits, float* __restrict__ hs_out,
                 float* __restrict__ ci_out) {
    extern __shared__ float sh[];
    const int tid = threadIdx.x, bid = blockIdx.x;
    int gen = *(volatile int*)&g_release;

    // ---- S0: embed + ss partials (blocks 0..31); zero g_dbc (others) ----
    if (bid < 32) {
        int idx = bid * NTHR + tid;
        int b = idx & 31;
        float v = emb[(size_t)token[b] * DD + (idx >> 5)];
        g_x[idx] = v;
        sh[tid] = v * v;
        __syncthreads();
        if (tid < 32) {
            float s = 0.f;
            #pragma unroll
            for (int j = 0; j < 32; j++) s += sh[j*32 + tid];
            g_sspart[bid*32 + tid] = s;
        }
    } else {
        int z = (bid - 32) * NTHR + tid;
        if (z < (RR + 2*NN) * BB) g_dbc[z] = 0.f;
    }
    gsync(gen);

    for (int l = 0; l < LNUM; l++) {
        // ---- SB: rms fold (1 warp) + in_proj GEMM -> 8 partials ----
        // DIAGNOSTIC: stage run TWICE (idempotent: identical direct stores).
        // dur_us delta vs R13 baseline == 24 x t_inproj (2nd pass L2-warm).
        rms_reduce();
        gemm_stage<0>(ipw + (size_t)l * 2*ED*DD, g_xzp, norm_w + (size_t)l * DD,
                      2*ED, DD, 128, 8, 512, sh);
        gemm_stage<0>(ipw + (size_t)l * 2*ED*DD, g_xzp, norm_w + (size_t)l * DD,
                      2*ED, DD, 128, 8, 512, sh);
        gsync(gen);

        // ---- SC: conv + silu + ci_out + x_proj partials ----
        {
            int lt = tid & 127, sbl = tid >> 7;
            int sb = sbl * NBLK + bid;
            float* xc = sh + sbl * SBSTRIDE;   // 8 x 33
            float* wsx = xc + 264;             // 8 x 96 (e-major)
            const float* cwl = cw + (size_t)l * ED * 4;
            const float* cbl = cb + (size_t)l * ED;
            const float* cil = ci + (size_t)l * BB * ED * 3;
            float* col = ci_out + (size_t)l * BB * ED * 3;
            const float* xwl = xpw + (size_t)l * (RR + 2*NN) * ED;
            if (sb < 256) {
                int e0 = sb * 8;
                #pragma unroll
                for (int it = 0; it < 2; it++) {
                    int item = lt + 128 * it;
                    int el = item & 7, b = item >> 3;
                    int e = e0 + el;
                    float sum = 0.f;
                    #pragma unroll
                    for (int ks = 0; ks < 8; ks++)
                        sum += g_xzp[ks*XZP_OFF + e*32 + b];
                    float xi = g_rms[b] * sum;
                    const float* cip = cil + ((size_t)b * ED + e) * 3;
                    float c0 = cip[0], c1 = cip[1], c2 = cip[2];
                    float4 w4 = *(const float4*)(cwl + e*4);
                    float pre = c0*w4.x + c1*w4.y + c2*w4.z + xi*w4.w + cbl[e];
                    float v = pre * sigf(pre);
                    xc[el*33 + b] = v;
                    g_xc[e*32 + b] = v;
                    float* cop = col + ((size_t)b * ED + e) * 3;
                    cop[0] = c1; cop[1] = c2; cop[2] = xi;
                }
                #pragma unroll
                for (int i = lt; i < 192; i += 128) {
                    int rr = i >> 1, eq = i & 1;
                    float4 v = *(const float4*)(xwl + (size_t)rr * ED + e0 + eq*4);
                    wsx[(eq*4+0)*96 + rr] = v.x;
                    wsx[(eq*4+1)*96 + rr] = v.y;
                    wsx[(eq*4+2)*96 + rr] = v.z;
                    wsx[(eq*4+3)*96 + rr] = v.w;
                }
                barsub(sbl);
                int b = lt & 31, rg = lt >> 5;   // rg 0..3
                float acc[24];
                #pragma unroll
                for (int j = 0; j < 24; j++) acc[j] = 0.f;
                #pragma unroll
                for (int k = 0; k < 8; k++) {
                    float xv = xc[k*33 + b];
                    #pragma unroll
                    for (int j = 0; j < 24; j++)
                        acc[j] += wsx[k*96 + rg + 4*j] * xv;
                }
                #pragma unroll
                for (int j = 0; j < 24; j++)
                    atomicAdd(&g_dbc[(rg + 4*j)*32 + b], acc[j]);
            }
        }
        gsync(gen);

        // ---- SD: dt_proj + softplus + SSM + gate ----
        {
            int idx = bid * NTHR + tid;
            if (idx < ED * BB) {
                int e = idx & (ED - 1), b = idx >> 11;
                const float* dtwl = dtw + (size_t)l * ED * RR;
                float acc = dtb[(size_t)l * ED + e];
                const float4* dwp = (const float4*)(dtwl + (size_t)e * RR);
                #pragma unroll
                for (int k = 0; k < 16; k++) {
                    float4 w4 = dwp[k];
                    acc += w4.x * g_dbc[(4*k+0)*32 + b];
                    acc += w4.y * g_dbc[(4*k+1)*32 + b];
                    acc += w4.z * g_dbc[(4*k+2)*32 + b];
                    acc += w4.w * g_dbc[(4*k+3)*32 + b];
                }
                float delta = (acc > 20.f) ? acc : __logf(1.f + __expf(acc));
                float xcv = g_xc[e*32 + b];
                float dxc = delta * xcv;
                const float4* hp = (const float4*)(hs + (size_t)l*BB*ED*NN
                                                      + ((size_t)b*ED + e)*NN);
                float4* ho = (float4*)(hs_out + (size_t)l*BB*ED*NN
                                              + ((size_t)b*ED + e)*NN);
                const float4* ap = (const float4*)(alog + (size_t)l*ED*NN
                                                        + (size_t)e*NN);
                float y = 0.f;
                #pragma unroll
                for (int q = 0; q < 4; q++) {
                    float4 h4 = hp[q], a4 = ap[q], o4;
                    float dA0 = __expf(delta * -__expf(a4.x));
                    float dA1 = __expf(delta * -__expf(a4.y));
                    float dA2 = __expf(delta * -__expf(a4.z));
                    float dA3 = __expf(delta * -__expf(a4.w));
                    int n0 = 4*q;
                    o4.x = dA0*h4.x + dxc * g_dbc[(RR+n0+0)*32 + b];
                    o4.y = dA1*h4.y + dxc * g_dbc[(RR+n0+1)*32 + b];
                    o4.z = dA2*h4.z + dxc * g_dbc[(RR+n0+2)*32 + b];
                    o4.w = dA3*h4.w + dxc * g_dbc[(RR+n0+3)*32 + b];
                    ho[q] = o4;
                    y += o4.x * g_dbc[(RR+NN+n0+0)*32 + b];
                    y += o4.y * g_dbc[(RR+NN+n0+1)*32 + b];
                    y += o4.z * g_dbc[(RR+NN+n0+2)*32 + b];
                    y += o4.w * g_dbc[(RR+NN+n0+3)*32 + b];
                }
                y += Dp[(size_t)l * ED + e] * xcv;
                float zsum = 0.f;
                #pragma unroll
                for (int ks = 0; ks < 8; ks++)
                    zsum += g_xzp[ks*XZP_OFF + (ED + e)*32 + b];
                float z = g_rms[b] * zsum;
                g_g[e*32 + b] = y * (z * sigf(z));
            }
        }
        gsync(gen);

        // ---- SE: out_proj GEMM -> 16 partials ----
        gemm_stage<1>(opw + (size_t)l * DD * ED, g_xp, g_x /*unused*/,
                      DD, ED, 128, 16, 256, sh);
        gsync(gen);

        // ---- SA: residual reduce + ss partials (blocks 0..31); zero dbc ----
        if (bid < 32) {
            int i = bid * NTHR + tid;
            float x = g_x[i];
            #pragma unroll
            for (int ks = 0; ks < 16; ks++) x += g_xp[ks*XP_OFF + i];
            g_x[i] = x;
            sh[tid] = x * x;
            __syncthreads();
            if (tid < 32) {
                float s = 0.f;
                #pragma unroll
                for (int j = 0; j < 32; j++) s += sh[j*32 + tid];
                g_sspart[bid*32 + tid] = s;
            }
        } else {
            int z = (bid - 32) * NTHR + tid;
            if (z < (RR + 2*NN) * BB) g_dbc[z] = 0.f;
        }
        gsync(gen);
    }

    // ---- logits stage: rms fold + GEMM (K-split 3, raw partials) ----
    rms_reduce();
    gemm_stage<2>(emb, logits, nfw, VV, DD, 0, 3, 2358, sh);
    gsync(gen);

    // ---- reduce 3 K-partials, apply final rms ----
    {
        float4* lg = (float4*)logits;
        const float4* p0 = (const float4*)g_lp0;
        const float4* p1 = (const float4*)g_lp1;
        int n4 = BB * VV / 4;
        for (int i = bid * NTHR + tid; i < n4; i += NBLK * NTHR) {
            int b = (i * 4) / VV;
            float r = g_rms[b];
            float4 a = lg[i], u = p0[i], v = p1[i];
            a.x = (a.x + u.x + v.x) * r;
            a.y = (a.y + u.y + v.y) * r;
            a.z = (a.z + u.z + v.z) * r;
            a.w = (a.w + u.w + v.w) * r;
            lg[i] = a;
        }
    }
}

// ---------------------------------------------------------------------------
extern "C" void kernel_launch(void* const* d_in, const int* in_sizes, int n_in,
                              void* d_out, int out_size) {
    const int*   token  = (const int*)  d_in[0];
    const float* hs     = (const float*)d_in[1];
    const float* ci     = (const float*)d_in[2];
    const float* emb    = (const float*)d_in[3];
    const float* norm_w = (const float*)d_in[4];
    const float* ipw    = (const float*)d_in[5];
    const float* cw     = (const float*)d_in[6];
    const float* cb     = (const float*)d_in[7];
    const float* xpw    = (const float*)d_in[8];
    const float* dtw    = (const float*)d_in[9];
    const float* dtb    = (const float*)d_in[10];
    const float* alog   = (const float*)d_in[11];
    const float* Dp     = (const float*)d_in[12];
    const float* opw    = (const float*)d_in[13];
    const float* nfw    = (const float*)d_in[14];

    float* out    = (float*)d_out;
    float* logits = out;
    float* hs_out = out + (size_t)BB * VV;
    float* ci_out = hs_out + (size_t)LNUM * BB * ED * NN;

    static int attr_set = 0;
    if (!attr_set) {
        cudaFuncSetAttribute(mega_kernel,
                             cudaFuncAttributeMaxDynamicSharedMemorySize,
                             SMEM_BYTES);
        attr_set = 1;
    }

    mega_kernel<<<NBLK, NTHR, SMEM_BYTES>>>(token, hs, ci, emb, norm_w, ipw,
                                            cw, cb, xpw, dtw, dtb, alog, Dp,
                                            opw, nfw, logits, hs_out, ci_out);
}

// round 15
// speedup vs baseline: 1.4482x; 1.4482x over previous
#include <cuda_runtime.h>
#include <cstdint>

#define LNUM 24
#define BB 32
#define DD 1024
#define ED 2048
#define NN 16
#define RR 64
#define VV 50280
#define NBLK 148
#define NTHR 1024
#define NSB (NBLK*8)
#define SBSTRIDE 5760            // floats per subblock: xs(1152) + 2x wbuf(2304)
#define SMEM_BYTES (8 * SBSTRIDE * 4)
#define XZP_OFF (2*ED*BB)        // 131072 floats per in_proj partial
#define XP_OFF  (DD*BB)          // 32768 floats per out_proj partial
#define KSIP 16                  // in_proj ksplit  -> 64*? : 64-row tiles, klen 64
#define KSOP 64                  // out_proj ksplit -> 64-row tiles, klen 32

typedef unsigned long long ull;

// -------- persistent scratch (feature-major, batch-minor [feat][32]) --------
__device__ float g_x  [DD*BB];
__device__ float g_xzp[KSIP * XZP_OFF];  // in_proj split-K partials
__device__ float g_xp [KSOP * XP_OFF];   // out_proj split-K partials
__device__ float g_xc [ED*BB];
__device__ float g_z  [ED*BB];           // silu(z) gate, presummed in SC
__device__ float g_dbc[(RR+2*NN)*BB];
__device__ float g_g  [ED*BB];
__device__ float g_sspart[32*BB];
__device__ float g_rms[BB];
__device__ float g_lp0[BB*VV];
__device__ float g_lp1[BB*VV];
__device__ int   g_flags[NBLK];
__device__ int   g_release;

// -------- f32x2 helpers --------
__device__ __forceinline__ ull dup2(float w) {
    ull r; asm("mov.b64 %0, {%1, %1};" : "=l"(r) : "f"(w)); return r;
}
__device__ __forceinline__ void fma2(ull &a, ull x, ull y) {
    asm("fma.rn.f32x2 %0, %1, %2, %0;" : "+l"(a) : "l"(x), "l"(y));
}
__device__ __forceinline__ float2 unpack2(ull v) {
    float lo, hi; asm("mov.b64 {%0, %1}, %2;" : "=f"(lo), "=f"(hi) : "l"(v));
    return make_float2(lo, hi);
}
__device__ __forceinline__ float sigf(float z) { return 1.f / (1.f + __expf(-z)); }

// -------- cp.async helpers --------
__device__ __forceinline__ void cpasync16(float* smem_dst, const float* gptr) {
    uint32_t a = (uint32_t)__cvta_generic_to_shared(smem_dst);
    asm volatile("cp.async.ca.shared.global [%0], [%1], 16;" :: "r"(a), "l"(gptr));
}
__device__ __forceinline__ void cpcommit() {
    asm volatile("cp.async.commit_group;");
}
template<int N>
__device__ __forceinline__ void cpwait() {
    asm volatile("cp.async.wait_group %0;" :: "n"(N));
}

__device__ __forceinline__ void barsub(int sbl) {
    asm volatile("bar.sync %0, %1;" :: "r"(sbl + 1), "r"(128) : "memory");
}

// -------- flag-based grid barrier (replay-safe via init-read) --------
__device__ __forceinline__ void gsync(int &gen) {
    __syncthreads();
    if (threadIdx.x == 0) {
        __threadfence();
        ((volatile int*)g_flags)[blockIdx.x] = gen + 1;
    }
    if (blockIdx.x == 0) {
        if (threadIdx.x < NBLK) {
            while (((volatile int*)g_flags)[threadIdx.x] - (gen + 1) < 0) { }
        }
        __syncthreads();
        if (threadIdx.x == 0) {
            __threadfence();
            *(volatile int*)&g_release = gen + 1;
        }
    } else {
        if (threadIdx.x == 0) {
            while (*(volatile int*)&g_release - (gen + 1) < 0) { }
            __threadfence();
        }
    }
    __syncthreads();
    gen = gen + 1;
}

// ---------------------------------------------------------------------------
// subblock GEMM: partial[ks][M][32] = W[M][k0:k0+klen] * X[k0:k0+klen][32]
// Tile = 64 rows x 32 b x klen; thread tile 2 rows x 8 b (8 f32x2 accs).
// W streamed GMEM->SMEM via coalesced cp.async, double-buffered.
// MODE 0: X = g_x * nw[k],  OUT = g_xzp + ks*XZP_OFF  (in_proj, 1024 tiles)
// MODE 1: X = g_g,          OUT = g_xp  + ks*XP_OFF   (out_proj, 1024 tiles)
// MODE 2: X = g_x * nw[k],  OUT = logits / g_lp0 / g_lp1 (K-split 3)
// ---------------------------------------------------------------------------
template<int MODE>
__device__ void gemm_stage(const float* __restrict__ W, float* __restrict__ OUT,
                           const float* __restrict__ nw,
                           int M, int Kdim, int kslice, int ksplit, int ntiles,
                           float* __restrict__ sh) {
    int lt  = threadIdx.x & 127;
    int sbl = threadIdx.x >> 7;
    int sb  = sbl * NBLK + blockIdx.x;
    int bg  = lt & 3, rg = lt >> 2;       // rg 0..31 -> 2 rows each
    int b0  = bg * 8;
    int lb  = lt & 31, kq = lt >> 5;
    float* xs  = sh + sbl * SBSTRIDE;     // 32 x 36
    float* wb0 = xs + 1152;               // 64 x 36
    float* wb1 = wb0 + 2304;              // 64 x 36
    int r_a = lt >> 3, c_a = lt & 7;      // cp.async: 4 rows/thread, coalesced

    for (int t = sb; t < ntiles; t += NSB) {
        int mt, ks, k0, klen;
        if (MODE == 2) {
            mt = t / 3; ks = t - mt * 3;
            k0 = ks * 352; klen = (ks == 2) ? 320 : 352;
        } else {
            mt = t / ksplit; ks = t - mt * ksplit;
            k0 = ks * kslice; klen = kslice;
        }
        int rbase = mt * 64;

        const float* wg[4];
        float* wd[4];
        #pragma unroll
        for (int j = 0; j < 4; j++) {
            int ra = rbase + r_a + j * 16; if (ra > M - 1) ra = M - 1;
            wg[j] = W + (size_t)ra * Kdim + k0 + c_a * 4;
            wd[j] = wb0 + (r_a + j * 16) * 36 + c_a * 4;
        }
        int nchunks = klen >> 5;

        // prologue: chunk 0 -> buf0
        #pragma unroll
        for (int j = 0; j < 4; j++) cpasync16(wd[j], wg[j]);
        cpcommit();

        ull acc[8];
        #pragma unroll
        for (int j = 0; j < 8; j++) acc[j] = 0ULL;

        for (int c = 0; c < nchunks; c++) {
            int kc = c << 5;
            #pragma unroll
            for (int i = 0; i < 8; i++) {
                int kk = kq + 4*i;
                int kgl = k0 + kc + kk;
                float v;
                if (MODE == 1) v = g_g[kgl*32 + lb];
                else           v = g_x[kgl*32 + lb] * nw[kgl];
                xs[kk*36 + lb] = v;
            }
            if (c + 1 < nchunks) {
                int off = 2304 * ((c + 1) & 1);
                #pragma unroll
                for (int j = 0; j < 4; j++)
                    cpasync16(wd[j] + off, wg[j] + kc + 32);
                cpcommit();
                cpwait<1>();
            } else {
                cpwait<0>();
            }
            barsub(sbl);

            const float* wb = (c & 1) ? wb1 : wb0;
            const float* wrA = wb + (rg*2) * 36;
            const float* wrB = wrA + 36;
            #pragma unroll
            for (int q = 0; q < 8; q++) {
                float4 wa = *(const float4*)(wrA + q*4);
                float4 wv = *(const float4*)(wrB + q*4);
                #pragma unroll
                for (int tt = 0; tt < 4; tt++) {
                    int kk = q*4 + tt;
                    ulonglong2 q0 = *(const ulonglong2*)&xs[kk*36 + b0];
                    ulonglong2 q1 = *(const ulonglong2*)&xs[kk*36 + b0 + 4];
                    float fa = (tt==0)?wa.x:(tt==1)?wa.y:(tt==2)?wa.z:wa.w;
                    float fb = (tt==0)?wv.x:(tt==1)?wv.y:(tt==2)?wv.z:wv.w;
                    ull da = dup2(fa), db = dup2(fb);
                    fma2(acc[0], da, q0.x); fma2(acc[1], da, q0.y);
                    fma2(acc[2], da, q1.x); fma2(acc[3], da, q1.y);
                    fma2(acc[4], db, q0.x); fma2(acc[5], db, q0.y);
                    fma2(acc[6], db, q1.x); fma2(acc[7], db, q1.y);
                }
            }
            barsub(sbl);
        }

        int r0 = rbase + rg*2, r1 = r0 + 1;
        if (MODE == 2) {
            float* outp = (ks == 0) ? OUT : ((ks == 1) ? g_lp0 : g_lp1);
            #pragma unroll
            for (int rr = 0; rr < 2; rr++) {
                int r = (rr == 0) ? r0 : r1;
                if (r < M) {
                    float2 a0 = unpack2(acc[rr*4+0]), a1 = unpack2(acc[rr*4+1]);
                    float2 a2 = unpack2(acc[rr*4+2]), a3 = unpack2(acc[rr*4+3]);
                    outp[(size_t)(b0+0)*VV + r] = a0.x;
                    outp[(size_t)(b0+1)*VV + r] = a0.y;
                    outp[(size_t)(b0+2)*VV + r] = a1.x;
                    outp[(size_t)(b0+3)*VV + r] = a1.y;
                    outp[(size_t)(b0+4)*VV + r] = a2.x;
                    outp[(size_t)(b0+5)*VV + r] = a2.y;
                    outp[(size_t)(b0+6)*VV + r] = a3.x;
                    outp[(size_t)(b0+7)*VV + r] = a3.y;
                }
            }
        } else {
            float* outp = OUT + (size_t)ks * ((MODE == 0) ? XZP_OFF : XP_OFF);
            #pragma unroll
            for (int rr = 0; rr < 2; rr++) {
                int r = (rr == 0) ? r0 : r1;
                float2 a0 = unpack2(acc[rr*4+0]), a1 = unpack2(acc[rr*4+1]);
                float2 a2 = unpack2(acc[rr*4+2]), a3 = unpack2(acc[rr*4+3]);
                *(float4*)&outp[r*32 + b0]     = make_float4(a0.x, a0.y, a1.x, a1.y);
                *(float4*)&outp[r*32 + b0 + 4] = make_float4(a2.x, a2.y, a3.x, a3.y);
            }
        }
    }
}

// rms reduce: one warp folds 32 per-block partials into g_rms
__device__ __forceinline__ void rms_reduce() {
    if (blockIdx.x == 0 && threadIdx.x < 32) {
        float s = 0.f;
        #pragma unroll
        for (int j = 0; j < 32; j++) s += g_sspart[j*32 + threadIdx.x];
        g_rms[threadIdx.x] = rsqrtf(s * (1.f/(float)DD) + 1e-5f);
    }
}

// ---------------------------------------------------------------------------
__global__ __launch_bounds__(NTHR, 1)
void mega_kernel(const int* __restrict__ token, const float* __restrict__ hs,
                 const float* __restrict__ ci, const float* __restrict__ emb,
                 const float* __restrict__ norm_w, const float* __restrict__ ipw,
                 const float* __restrict__ cw, const float* __restrict__ cb,
                 const float* __restrict__ xpw, const float* __restrict__ dtw,
                 const float* __restrict__ dtb, const float* __restrict__ alog,
                 const float* __restrict__ Dp, const float* __restrict__ opw,
                 const float* __restrict__ nfw,
                 float* __restrict__ logits, float* __restrict__ hs_out,
                 float* __restrict__ ci_out) {
    extern __shared__ float sh[];
    const int tid = threadIdx.x, bid = blockIdx.x;
    int gen = *(volatile int*)&g_release;

    // ---- S0: embed + ss partials (blocks 0..31); zero g_dbc (others) ----
    if (bid < 32) {
        int idx = bid * NTHR + tid;
        int b = idx & 31;
        float v = emb[(size_t)token[b] * DD + (idx >> 5)];
        g_x[idx] = v;
        sh[tid] = v * v;
        __syncthreads();
        if (tid < 32) {
            float s = 0.f;
            #pragma unroll
            for (int j = 0; j < 32; j++) s += sh[j*32 + tid];
            g_sspart[bid*32 + tid] = s;
        }
    } else {
        int z = (bid - 32) * NTHR + tid;
        if (z < (RR + 2*NN) * BB) g_dbc[z] = 0.f;
    }
    gsync(gen);

    for (int l = 0; l < LNUM; l++) {
        // ---- SB: rms fold (1 warp) + in_proj GEMM -> 16 partials, 1024 tiles ----
        rms_reduce();
        gemm_stage<0>(ipw + (size_t)l * 2*ED*DD, g_xzp, norm_w + (size_t)l * DD,
                      2*ED, DD, 64, KSIP, 1024, sh);
        gsync(gen);

        // ---- SC: conv + silu + ci_out + z-gate presum + x_proj partials ----
        {
            int lt = tid & 127, sbl = tid >> 7;
            int sb = sbl * NBLK + bid;
            float* xc = sh + sbl * SBSTRIDE;   // 8 x 33
            float* wsx = xc + 264;             // 8 x 96 (e-major)
            const float* cwl = cw + (size_t)l * ED * 4;
            const float* cbl = cb + (size_t)l * ED;
            const float* cil = ci + (size_t)l * BB * ED * 3;
            float* col = ci_out + (size_t)l * BB * ED * 3;
            const float* xwl = xpw + (size_t)l * (RR + 2*NN) * ED;
            if (sb < 256) {
                int e0 = sb * 8;
                #pragma unroll
                for (int it = 0; it < 2; it++) {
                    int item = lt + 128 * it;
                    int el = item & 7, b = item >> 3;
                    int e = e0 + el;
                    float rmsb = g_rms[b];
                    float sum = 0.f, zs = 0.f;
                    #pragma unroll
                    for (int ks = 0; ks < KSIP; ks++) {
                        sum += g_xzp[ks*XZP_OFF + e*32 + b];
                        zs  += g_xzp[ks*XZP_OFF + (ED + e)*32 + b];
                    }
                    float xi = rmsb * sum;
                    float zz = rmsb * zs;
                    g_z[e*32 + b] = zz * sigf(zz);
                    const float* cip = cil + ((size_t)b * ED + e) * 3;
                    float c0 = cip[0], c1 = cip[1], c2 = cip[2];
                    float4 w4 = *(const float4*)(cwl + e*4);
                    float pre = c0*w4.x + c1*w4.y + c2*w4.z + xi*w4.w + cbl[e];
                    float v = pre * sigf(pre);
                    xc[el*33 + b] = v;
                    g_xc[e*32 + b] = v;
                    float* cop = col + ((size_t)b * ED + e) * 3;
                    cop[0] = c1; cop[1] = c2; cop[2] = xi;
                }
                #pragma unroll
                for (int i = lt; i < 192; i += 128) {
                    int rr = i >> 1, eq = i & 1;
                    float4 v = *(const float4*)(xwl + (size_t)rr * ED + e0 + eq*4);
                    wsx[(eq*4+0)*96 + rr] = v.x;
                    wsx[(eq*4+1)*96 + rr] = v.y;
                    wsx[(eq*4+2)*96 + rr] = v.z;
                    wsx[(eq*4+3)*96 + rr] = v.w;
                }
                barsub(sbl);
                int b = lt & 31, rg = lt >> 5;   // rg 0..3
                float acc[24];
                #pragma unroll
                for (int j = 0; j < 24; j++) acc[j] = 0.f;
                #pragma unroll
                for (int k = 0; k < 8; k++) {
                    float xv = xc[k*33 + b];
                    #pragma unroll
                    for (int j = 0; j < 24; j++)
                        acc[j] += wsx[k*96 + rg + 4*j] * xv;
                }
                #pragma unroll
                for (int j = 0; j < 24; j++)
                    atomicAdd(&g_dbc[(rg + 4*j)*32 + b], acc[j]);
            }
        }
        gsync(gen);

        // ---- SD: dt_proj + softplus + SSM + gate (2 threads per (b,e)) ----
        {
            int slot = bid * NTHR + tid;
            if (slot < 2 * ED * BB) {          // 131072 slots = 128 full blocks
                int h = slot & 1;
                int p = slot >> 1;
                int e = p & (ED - 1), b = p >> 11;
                const float4* dwp = (const float4*)(dtw + (size_t)l * ED * RR
                                                        + (size_t)e * RR + h * 32);
                float acc = 0.f;
                #pragma unroll
                for (int k4 = 0; k4 < 8; k4++) {
                    float4 w4 = dwp[k4];
                    int kb = h*32 + k4*4;
                    acc += w4.x * g_dbc[(kb+0)*32 + b];
                    acc += w4.y * g_dbc[(kb+1)*32 + b];
                    acc += w4.z * g_dbc[(kb+2)*32 + b];
                    acc += w4.w * g_dbc[(kb+3)*32 + b];
                }
                acc += __shfl_xor_sync(0xffffffffu, acc, 1);
                acc += dtb[(size_t)l * ED + e];
                float delta = (acc > 20.f) ? acc : __logf(1.f + __expf(acc));
                float xcv = g_xc[e*32 + b];
                float dxc = delta * xcv;
                const float4* hp = (const float4*)(hs + (size_t)l*BB*ED*NN
                                            + ((size_t)b*ED + e)*NN + h*8);
                float4* ho = (float4*)(hs_out + (size_t)l*BB*ED*NN
                                            + ((size_t)b*ED + e)*NN + h*8);
                const float4* ap = (const float4*)(alog + (size_t)l*ED*NN
                                            + (size_t)e*NN + h*8);
                float y = 0.f;
                #pragma unroll
                for (int q = 0; q < 2; q++) {
                    float4 h4 = hp[q], a4 = ap[q], o4;
                    float dA0 = __expf(delta * -__expf(a4.x));
                    float dA1 = __expf(delta * -__expf(a4.y));
                    float dA2 = __expf(delta * -__expf(a4.z));
                    float dA3 = __expf(delta * -__expf(a4.w));
                    int n0 = h*8 + 4*q;
                    o4.x = dA0*h4.x + dxc * g_dbc[(RR+n0+0)*32 + b];
                    o4.y = dA1*h4.y + dxc * g_dbc[(RR+n0+1)*32 + b];
                    o4.z = dA2*h4.z + dxc * g_dbc[(RR+n0+2)*32 + b];
                    o4.w = dA3*h4.w + dxc * g_dbc[(RR+n0+3)*32 + b];
                    ho[q] = o4;
                    y += o4.x * g_dbc[(RR+NN+n0+0)*32 + b];
                    y += o4.y * g_dbc[(RR+NN+n0+1)*32 + b];
                    y += o4.z * g_dbc[(RR+NN+n0+2)*32 + b];
                    y += o4.w * g_dbc[(RR+NN+n0+3)*32 + b];
                }
                y += __shfl_xor_sync(0xffffffffu, y, 1);
                if (h == 0) {
                    y += Dp[(size_t)l * ED + e] * xcv;
                    g_g[e*32 + b] = y * g_z[e*32 + b];
                }
            }
        }
        gsync(gen);

        // ---- SE: out_proj GEMM -> 64 partials, 1024 tiles ----
        gemm_stage<1>(opw + (size_t)l * DD * ED, g_xp, g_x /*unused*/,
                      DD, ED, 32, KSOP, 1024, sh);
        gsync(gen);

        // ---- SA: residual reduce + ss partials (blocks 0..31); zero dbc ----
        if (bid < 32) {
            int i = bid * NTHR + tid;
            float x = g_x[i];
            #pragma unroll
            for (int ks = 0; ks < KSOP; ks++) x += g_xp[ks*XP_OFF + i];
            g_x[i] = x;
            sh[tid] = x * x;
            __syncthreads();
            if (tid < 32) {
                float s = 0.f;
                #pragma unroll
                for (int j = 0; j < 32; j++) s += sh[j*32 + tid];
                g_sspart[bid*32 + tid] = s;
            }
        } else {
            int z = (bid - 32) * NTHR + tid;
            if (z < (RR + 2*NN) * BB) g_dbc[z] = 0.f;
        }
        gsync(gen);
    }

    // ---- logits stage: rms fold + GEMM (K-split 3, raw partials) ----
    rms_reduce();
    gemm_stage<2>(emb, logits, nfw, VV, DD, 0, 3, 2358, sh);
    gsync(gen);

    // ---- reduce 3 K-partials, apply final rms ----
    {
        float4* lg = (float4*)logits;
        const float4* p0 = (const float4*)g_lp0;
        const float4* p1 = (const float4*)g_lp1;
        int n4 = BB * VV / 4;
        for (int i = bid * NTHR + tid; i < n4; i += NBLK * NTHR) {
            int b = (i * 4) / VV;
            float r = g_rms[b];
            float4 a = lg[i], u = p0[i], v = p1[i];
            a.x = (a.x + u.x + v.x) * r;
            a.y = (a.y + u.y + v.y) * r;
            a.z = (a.z + u.z + v.z) * r;
            a.w = (a.w + u.w + v.w) * r;
            lg[i] = a;
        }
    }
}

// ---------------------------------------------------------------------------
extern "C" void kernel_launch(void* const* d_in, const int* in_sizes, int n_in,
                              void* d_out, int out_size) {
    const int*   token  = (const int*)  d_in[0];
    const float* hs     = (const float*)d_in[1];
    const float* ci     = (const float*)d_in[2];
    const float* emb    = (const float*)d_in[3];
    const float* norm_w = (const float*)d_in[4];
    const float* ipw    = (const float*)d_in[5];
    const float* cw     = (const float*)d_in[6];
    const float* cb     = (const float*)d_in[7];
    const float* xpw    = (const float*)d_in[8];
    const float* dtw    = (const float*)d_in[9];
    const float* dtb    = (const float*)d_in[10];
    const float* alog   = (const float*)d_in[11];
    const float* Dp     = (const float*)d_in[12];
    const float* opw    = (const float*)d_in[13];
    const float* nfw    = (const float*)d_in[14];

    float* out    = (float*)d_out;
    float* logits = out;
    float* hs_out = out + (size_t)BB * VV;
    float* ci_out = hs_out + (size_t)LNUM * BB * ED * NN;

    static int attr_set = 0;
    if (!attr_set) {
        cudaFuncSetAttribute(mega_kernel,
                             cudaFuncAttributeMaxDynamicSharedMemorySize,
                             SMEM_BYTES);
        attr_set = 1;
    }

    mega_kernel<<<NBLK, NTHR, SMEM_BYTES>>>(token, hs, ci, emb, norm_w, ipw,
                                            cw, cb, xpw, dtw, dtb, alog, Dp,
                                            opw, nfw, logits, hs_out, ci_out);
}